// round 2
// baseline (speedup 1.0000x reference)
#include <cuda_runtime.h>
#include <cuda_bf16.h>

#define NUM_CLASSES 1000
#define FEAT_DIM    512
#define BATCH       65536

// scratch (no allocations allowed)
__device__ float g_sums[NUM_CLASSES];
__device__ int   g_counts[NUM_CLASSES];

__global__ void zero_kernel() {
    int i = threadIdx.x;
    if (i < NUM_CLASSES) {
        g_sums[i]   = 0.0f;
        g_counts[i] = 0;
    }
}

// one warp per sample; 8 warps per block. Accumulates per-class raw sums + counts.
__global__ __launch_bounds__(256) void dist_kernel(
    const float4* __restrict__ feat,
    const float4* __restrict__ cent,
    const long long* __restrict__ labels)
{
    const int tid    = blockIdx.x * blockDim.x + threadIdx.x;
    const int sample = tid >> 5;
    const int lane   = threadIdx.x & 31;

    const int lbl = (int)labels[sample];   // broadcast load (all lanes same addr)

    const float4* fr = feat + (size_t)sample * (FEAT_DIM / 4);
    const float4* cr = cent + (size_t)lbl    * (FEAT_DIM / 4);

    float acc = 0.0f;
#pragma unroll
    for (int k = 0; k < 4; k++) {
        float4 a = __ldcs(fr + lane + 32 * k);   // streaming: evict-first
        float4 b = __ldg (cr + lane + 32 * k);   // centers: keep L2-resident
        float dx = a.x - b.x;
        float dy = a.y - b.y;
        float dz = a.z - b.z;
        float dw = a.w - b.w;
        acc = fmaf(dx, dx, acc);
        acc = fmaf(dy, dy, acc);
        acc = fmaf(dz, dz, acc);
        acc = fmaf(dw, dw, acc);
    }

    // warp reduce
#pragma unroll
    for (int off = 16; off > 0; off >>= 1)
        acc += __shfl_xor_sync(0xFFFFFFFFu, acc, off);

    if (lane == 0) {
        atomicAdd(&g_sums[lbl], acc);
        atomicAdd(&g_counts[lbl], 1);
    }
}

// single block: per-class normalize + reduce to scalar
__global__ __launch_bounds__(1024) void finalize_kernel(float* __restrict__ out) {
    const int j = threadIdx.x;
    float v = 0.0f;
    if (j < NUM_CLASSES) {
        int c = g_counts[j];
        if (c > 0)
            v = g_sums[j] / ((float)c * (float)FEAT_DIM * (float)BATCH);
    }

    // block reduce
#pragma unroll
    for (int off = 16; off > 0; off >>= 1)
        v += __shfl_xor_sync(0xFFFFFFFFu, v, off);

    __shared__ float s[32];
    if ((j & 31) == 0) s[j >> 5] = v;
    __syncthreads();

    if (j < 32) {
        float t = s[j];
#pragma unroll
        for (int off = 16; off > 0; off >>= 1)
            t += __shfl_xor_sync(0xFFFFFFFFu, t, off);
        if (j == 0) out[0] = t;
    }
}

extern "C" void kernel_launch(void* const* d_in, const int* in_sizes, int n_in,
                              void* d_out, int out_size) {
    const float4*    feat   = (const float4*)d_in[0];
    const float4*    cent   = (const float4*)d_in[1];
    const long long* labels = (const long long*)d_in[2];
    float* out = (float*)d_out;

    zero_kernel<<<1, 1024>>>();
    dist_kernel<<<BATCH / 8, 256>>>(feat, cent, labels);
    finalize_kernel<<<1, 1024>>>(out);
}

// round 4
// speedup vs baseline: 1.0720x; 1.0720x over previous
#include <cuda_runtime.h>
#include <cuda_bf16.h>

#define NUM_CLASSES 1000
#define FEAT_DIM    512
#define BATCH       65536
#define BANKS       16

// scratch (no allocations allowed) — banked per-class accumulators
__device__ float g_sums[NUM_CLASSES * BANKS];
__device__ int   g_cnts[NUM_CLASSES * BANKS];

__global__ void zero_kernel() {
    int i = blockIdx.x * blockDim.x + threadIdx.x;
    if (i < NUM_CLASSES * BANKS) {
        g_sums[i] = 0.0f;
        g_cnts[i] = 0;
    }
}

// one warp per sample; 8 warps per block. Banked per-class raw sums + counts.
__global__ __launch_bounds__(256) void dist_kernel(
    const float4* __restrict__ feat,
    const float4* __restrict__ cent,
    const long long* __restrict__ labels)
{
    const int tid    = blockIdx.x * blockDim.x + threadIdx.x;
    const int sample = tid >> 5;
    const int lane   = threadIdx.x & 31;
    const int bank   = blockIdx.x & (BANKS - 1);

    const int lbl = (int)labels[sample];   // broadcast load (all lanes same addr)

    const float4* fr = feat + (size_t)sample * (FEAT_DIM / 4);
    const float4* cr = cent + (size_t)lbl    * (FEAT_DIM / 4);

    float acc = 0.0f;
#pragma unroll
    for (int k = 0; k < 4; k++) {
        float4 a = fr[lane + 32 * k];      // plain loads (R1 measured-good path)
        float4 b = cr[lane + 32 * k];
        float dx = a.x - b.x;
        float dy = a.y - b.y;
        float dz = a.z - b.z;
        float dw = a.w - b.w;
        acc = fmaf(dx, dx, acc);
        acc = fmaf(dy, dy, acc);
        acc = fmaf(dz, dz, acc);
        acc = fmaf(dw, dw, acc);
    }

    // warp reduce
#pragma unroll
    for (int off = 16; off > 0; off >>= 1)
        acc += __shfl_xor_sync(0xFFFFFFFFu, acc, off);

    if (lane == 0) {
        atomicAdd(&g_sums[lbl * BANKS + bank], acc);
        atomicAdd(&g_cnts[lbl * BANKS + bank], 1);
    }
}

// single block: fold banks, per-class normalize, reduce to scalar
__global__ __launch_bounds__(1024) void finalize_kernel(float* __restrict__ out) {
    const int j = threadIdx.x;
    float v = 0.0f;
    if (j < NUM_CLASSES) {
        float s = 0.0f;
        int   c = 0;
#pragma unroll
        for (int b = 0; b < BANKS; b++) {
            s += g_sums[j * BANKS + b];
            c += g_cnts[j * BANKS + b];
        }
        if (c > 0)
            v = s / ((float)c * (float)FEAT_DIM * (float)BATCH);
    }

    // block reduce
#pragma unroll
    for (int off = 16; off > 0; off >>= 1)
        v += __shfl_xor_sync(0xFFFFFFFFu, v, off);

    __shared__ float sh[32];
    if ((j & 31) == 0) sh[j >> 5] = v;
    __syncthreads();

    if (j < 32) {
        float t = sh[j];
#pragma unroll
        for (int off = 16; off > 0; off >>= 1)
            t += __shfl_xor_sync(0xFFFFFFFFu, t, off);
        if (j == 0) out[0] = t;
    }
}

extern "C" void kernel_launch(void* const* d_in, const int* in_sizes, int n_in,
                              void* d_out, int out_size) {
    const float4*    feat   = (const float4*)d_in[0];
    const float4*    cent   = (const float4*)d_in[1];
    const long long* labels = (const long long*)d_in[2];
    float* out = (float*)d_out;

    zero_kernel<<<(NUM_CLASSES * BANKS + 1023) / 1024, 1024>>>();
    dist_kernel<<<BATCH / 8, 256>>>(feat, cent, labels);
    finalize_kernel<<<1, 1024>>>(out);
}